// round 17
// baseline (speedup 1.0000x reference)
#include <cuda_runtime.h>
#include <stdint.h>

// MultiEchoNeighborBlock: per-pixel 7x7 KNN (k=9) over point distances,
// gather range values in exact rank order, 20->32 linear + leaky relu.
//
// R17 vs R16 (137.6us, issue=75.4, alu=66.7, fma=37.4, occ=44.9):
// ECHO-SPLIT THREADING. Evidence: 5-op insert stage is the op floor; the
// remaining gap is idle issue slots from serial insert-chain dependencies
// (2 chains/thread), and R10 proved per-thread chain-splitting blows regs.
// Fix: 2 threads per pixel (512-thr blocks, echo = tid&1), ONE chain per
// thread (18-reg array pair), occ -> 50% at 64 regs, 2x independent chains
// per register. Distances scalar per thread (R13-validated exact chain:
// __fadd_rn/__fmul_rn, ref sum order, IEEE sqrt). Linear layer: per-thread
// partial over its 10 features (FFMA2, exact), lane-pair shfl_xor(1) + ADD2
// combine (<=1ulp output-side reorder, never an ordering decision).
// Flavor: insA at dx==0, insF otherwise -> alu ~= fma per candidate.
// Stable-insert semantics unchanged (R5 proof).

#define HH 64
#define WW 2048
#define HWP (HH * WW)
#define NCH 8
#define BX 128
#define BY 2
#define NPIX (BX * BY)      // 256 pixels per block
#define TPB (NPIX * 2)      // 512 threads: 2 per pixel
#define TW (BX + 6)
#define TH (BY + 6)

#define PACK2S(out, v) \
    asm("mov.b64 %0, {%1, %1};" : "=l"(out) : "r"(__float_as_uint(v)))
#define UNPACK2(lo, hi, in) \
    do { unsigned _ulo, _uhi; \
         asm("mov.b64 {%0, %1}, %2;" : "=r"(_ulo), "=r"(_uhi) : "l"(in)); \
         lo = __uint_as_float(_ulo); hi = __uint_as_float(_uhi); } while (0)
#define ADD2(out, a, b) asm("add.rn.f32x2 %0, %1, %2;" : "=l"(out) : "l"(a), "l"(b))
#define FMA2(out, a, b, c) \
    asm("fma.rn.f32x2 %0, %1, %2, %3;" : "=l"(out) : "l"(a), "l"(b), "l"(c))

// alu-flavor stable insert (M stages): 1 FSETP + 4 SEL. Independent per-slot
// predicates (array sorted => kin<ak[j] monotone in j). Ties: incoming
// (later index) sinks below equal residents; residents never re-compared
// -> exact top_k stable order (R5 proof).
template <int M>
__device__ __forceinline__ void insA(float kin, float vin,
                                     float (&ak)[9], float (&av)[9]) {
    float ck = kin, cv = vin;
#pragma unroll
    for (int j = 0; j < M; ++j) {
        bool pj = kin < ak[j];
        float tk = ak[j], tv = av[j];
        ak[j] = pj ? ck : tk;
        av[j] = pj ? cv : tv;
        ck = pj ? tk : ck;
        cv = pj ? tv : cv;
    }
}

// fma-flavor stable insert (M stages): FSET + 2 FMNMX (alu) + FADD + 2 FFMA
// (fma). Mask uses ORIGINAL kin; FFMA blends are value-moves (<=1ulp,
// payloads only feed the linear layer, never an ordering decision).
template <int M>
__device__ __forceinline__ void insF(float kin, float vin,
                                     float (&ak)[9], float (&av)[9]) {
    float ck = kin, cv = vin;
#pragma unroll
    for (int j = 0; j < M; ++j) {
        float aj = ak[j];
        float m;
        asm("set.lt.f32.f32 %0, %1, %2;" : "=f"(m) : "f"(kin), "f"(aj));
        float mn = fminf(ck, aj);
        float mx = fmaxf(ck, aj);
        float diff = __fadd_rn(cv, -av[j]);
        av[j] = __fmaf_rn(m, diff, av[j]);
        cv    = __fmaf_rn(-m, diff, cv);
        ak[j] = mn;
        ck = mx;
    }
}

// One candidate for THIS thread's echo. Scalar distance, exact reference
// order (no contraction: __fadd_rn/__fmul_rn only), IEEE sqrt.
template <int M, int AF>
__device__ __forceinline__ void do_cand(const float4 p,
                                        float nqx, float nqy, float nqz,
                                        float (&ak)[9], float (&av)[9]) {
    float dx = __fadd_rn(p.x, nqx);   // (p - q); squares == (q - p)^2
    float dy = __fadd_rn(p.y, nqy);
    float dz = __fadd_rn(p.z, nqz);
    float s = __fadd_rn(__fadd_rn(__fmul_rn(dx, dx), __fmul_rn(dy, dy)),
                        __fmul_rn(dz, dz));
    float d = __fsqrt_rn(s);
    if (AF) insA<M>(d, p.w, ak, av);
    else    insF<M>(d, p.w, ak, av);
}

__global__ __launch_bounds__(TPB, 2)
void knn_block_kernel(const float* __restrict__ x,
                      const float* __restrict__ rw,
                      float* __restrict__ out) {
    __shared__ float4 tile[TH][TW];
    __shared__ float wt[20][32];

    const int tid = threadIdx.x;
    const int b = blockIdx.z;
    const int h0 = blockIdx.y * BY;
    const int w0 = blockIdx.x * BX;
    const float* X = x + (size_t)b * NCH * HWP;

    for (int i = tid; i < 640; i += TPB) {
        wt[i % 20][i / 20] = rw[i];
    }
    for (int i = tid; i < TH * TW; i += TPB) {
        int r = i / TW, c = i % TW;
        int gh = h0 - 3 + r, gw = w0 - 3 + c;
        float4 v = make_float4(0.f, 0.f, 0.f, 0.f);
        if (gh >= 0 && gh < HH && gw >= 0 && gw < WW) {
            int o = gh * WW + gw;
            v.x = X[2 * HWP + o];
            v.y = X[3 * HWP + o];
            v.z = X[4 * HWP + o];
            v.w = X[0 * HWP + o];
        }
        tile[r][c] = v;
    }
    __syncthreads();

    const int echo = tid & 1;          // lane pairs (2i, 2i+1) share a pixel
    const int pl = tid >> 1;           // pixel slot within block
    const int tx = pl % BX;
    const int ty = pl / BX;
    const int h = h0 + ty;
    const int w = w0 + tx;
    const int pix = h * WW + w;

    const float4 c4 = tile[ty + 3][tx + 3];
    float nqx, nqy, nqz, center;
    if (echo == 0) {
        nqx = -c4.x; nqy = -c4.y; nqz = -c4.z;
        center = c4.w;
    } else {
        nqx = -X[5 * HWP + pix];
        nqy = -X[6 * HWP + pix];
        nqz = -X[7 * HWP + pix];
        center = X[1 * HWP + pix];
    }

    const float INF = __int_as_float(0x7f800000);
    float ak[9], av[9];
#pragma unroll
    for (int j = 0; j < 9; ++j) { ak[j] = INF; av[j] = 0.f; }

    // Triangle phase: candidate i needs only min(i+1,9) chain stages.
    // Flavor: insA at dx==0, insF elsewhere (pipe balance for this mix).
    {
        const float4* r0 = &tile[ty + 0][tx];
        do_cand<1, 1>(r0[0], nqx, nqy, nqz, ak, av);
        do_cand<2, 0>(r0[1], nqx, nqy, nqz, ak, av);
        do_cand<3, 0>(r0[2], nqx, nqy, nqz, ak, av);
        do_cand<4, 0>(r0[3], nqx, nqy, nqz, ak, av);
        do_cand<5, 0>(r0[4], nqx, nqy, nqz, ak, av);
        do_cand<6, 0>(r0[5], nqx, nqy, nqz, ak, av);
        do_cand<7, 0>(r0[6], nqx, nqy, nqz, ak, av);
        const float4* r1 = &tile[ty + 1][tx];
        do_cand<8, 1>(r1[0], nqx, nqy, nqz, ak, av);
        do_cand<9, 0>(r1[1], nqx, nqy, nqz, ak, av);
        do_cand<9, 0>(r1[2], nqx, nqy, nqz, ak, av);
        do_cand<9, 0>(r1[3], nqx, nqy, nqz, ak, av);
        do_cand<9, 0>(r1[4], nqx, nqy, nqz, ak, av);
        do_cand<9, 0>(r1[5], nqx, nqy, nqz, ak, av);
        do_cand<9, 0>(r1[6], nqx, nqy, nqz, ak, av);
    }
    // Steady phase: rows 2..6.
#pragma unroll 1
    for (int dy = 2; dy < 7; ++dy) {
        const float4* row = &tile[ty + dy][tx];
        do_cand<9, 1>(row[0], nqx, nqy, nqz, ak, av);
        do_cand<9, 0>(row[1], nqx, nqy, nqz, ak, av);
        do_cand<9, 0>(row[2], nqx, nqy, nqz, ak, av);
        do_cand<9, 0>(row[3], nqx, nqy, nqz, ak, av);
        do_cand<9, 0>(row[4], nqx, nqy, nqz, ak, av);
        do_cand<9, 0>(row[5], nqx, nqy, nqz, ak, av);
        do_cand<9, 0>(row[6], nqx, nqy, nqz, ak, av);
    }

    // This thread's 10 features: 9 sorted payloads + its center range.
    float feats[10];
#pragma unroll
    for (int s = 0; s < 9; ++s) feats[s] = av[s];
    feats[9] = center;

    // Partial 10->32 linear (this echo's weight columns), packed FFMA2.
    const float* wbase = &wt[echo * 10][0];
    uint64_t acc2[16];
#pragma unroll
    for (int k = 0; k < 16; ++k) acc2[k] = 0ull;
#pragma unroll
    for (int c = 0; c < 10; ++c) {
        uint64_t f2;
        PACK2S(f2, feats[c]);
        const ulonglong2* wp = (const ulonglong2*)(wbase + c * 32);
#pragma unroll
        for (int k4 = 0; k4 < 8; ++k4) {
            ulonglong2 wv = wp[k4];
            FMA2(acc2[k4 * 2 + 0], f2, wv.x, acc2[k4 * 2 + 0]);
            FMA2(acc2[k4 * 2 + 1], f2, wv.y, acc2[k4 * 2 + 1]);
        }
    }

    // Lane-pair combine: echo0 keeps channels 0..15 (acc2[0..7]),
    // echo1 keeps 16..31 (acc2[8..15]); exchange the other half via
    // shfl_xor(1). ADD2 of two independent partial sums (no contraction).
    float* O = out + (size_t)b * 32 * HWP + pix;
#pragma unroll
    for (int j = 0; j < 8; ++j) {
        unsigned long long send = echo ? acc2[j] : acc2[j + 8];
        unsigned long long recv = __shfl_xor_sync(0xFFFFFFFFu, send, 1);
        unsigned long long mine = echo ? acc2[j + 8] : acc2[j];
        uint64_t tot;
        ADD2(tot, (uint64_t)mine, (uint64_t)recv);
        float v0, v1;
        UNPACK2(v0, v1, tot);
        v0 = fmaxf(v0, 0.01f * v0);   // leaky_relu(0.01)
        v1 = fmaxf(v1, 0.01f * v1);
        int k = 16 * echo + 2 * j;
        O[(size_t)(k + 0) * HWP] = v0;
        O[(size_t)(k + 1) * HWP] = v1;
    }
}

extern "C" void kernel_launch(void* const* d_in, const int* in_sizes, int n_in,
                              void* d_out, int out_size) {
    const float* x  = (const float*)d_in[0];
    const float* rw = (const float*)d_in[1];
    if (n_in >= 2 && in_sizes[0] == 640) {
        const float* t = x; x = rw; rw = t;
    }
    dim3 grid(WW / BX, HH / BY, 4);
    knn_block_kernel<<<grid, TPB>>>(x, rw, (float*)d_out);
}